// round 1
// baseline (speedup 1.0000x reference)
#include <cuda_runtime.h>
#include <cstdint>

// Problem constants (fixed by the dataset)
#define NN 250000
#define DD 128
#define FF 512
#define BB 5000

// Output layout (tuple order, row-major, concatenated):
//   M               : [BB]        offset 0
//   max_instances   : [BB*FF]     offset 5000
//   max_z_ins       : [BB*DD]     offset 2565000
//   loc_ins         : [NN]        offset 3205000
//   max_mu          : [BB*DD]     offset 3455000
//   max_std         : [BB*DD]     offset 4095000
#define OFF_M        0
#define OFF_INST     5000
#define OFF_Z        2565000
#define OFF_LOC      3205000
#define OFF_MU       3455000
#define OFF_STD      4095000

// Per-bag packed (encoded loc | (N - index)) argmax scratch.
__device__ unsigned long long g_seg[BB];

__global__ void init_seg_kernel() {
    int i = blockIdx.x * blockDim.x + threadIdx.x;
    if (i < BB) g_seg[i] = 0ULL;
}

// Order-preserving bijection float -> uint32 (monotonic, injective).
__device__ __forceinline__ unsigned enc_float(float f) {
    unsigned bits = __float_as_uint(f);
    return (bits & 0x80000000u) ? ~bits : (bits | 0x80000000u);
}
__device__ __forceinline__ float dec_float(unsigned e) {
    unsigned bits = (e & 0x80000000u) ? (e ^ 0x80000000u) : ~e;
    return __uint_as_float(bits);
}

// Warp per row: compute loc = dot(z_row, W) + b, write loc_ins,
// atomicMax packed (enc(loc), N-row) into the row's bag slot.
__global__ void loc_kernel(const float* __restrict__ z,
                           const int*   __restrict__ bag,
                           const float* __restrict__ W,
                           const float* __restrict__ b,
                           float*       __restrict__ loc_out) {
    int warp = (blockIdx.x * blockDim.x + threadIdx.x) >> 5;
    int lane = threadIdx.x & 31;
    if (warp >= NN) return;

    const float4 zv = reinterpret_cast<const float4*>(z + (size_t)warp * DD)[lane];
    const float4 wv = reinterpret_cast<const float4*>(W)[lane];  // L1-resident

    float s = fmaf(zv.x, wv.x, fmaf(zv.y, wv.y, fmaf(zv.z, wv.z, zv.w * wv.w)));
    #pragma unroll
    for (int off = 16; off; off >>= 1)
        s += __shfl_xor_sync(0xFFFFFFFFu, s, off);

    if (lane == 0) {
        s += b[0];
        loc_out[warp] = s;
        unsigned long long packed =
            ((unsigned long long)enc_float(s) << 32) | (unsigned)(NN - warp);
        atomicMax(&g_seg[bag[warp]], packed);
    }
}

// One block per bag: decode argmax, gather rows (float4 copies), write M.
// packed == 0 means empty bag (any real write has enc >= 0x007FFFFF and
// low word in [1, N], so 0 is unreachable by writes) -> zero fill.
__global__ void gather_kernel(const float* __restrict__ z,
                              const float* __restrict__ inst,
                              const float* __restrict__ mu,
                              const float* __restrict__ sd,
                              float*       __restrict__ out) {
    const int bagid = blockIdx.x;
    const int tid   = threadIdx.x;

    const unsigned long long p = g_seg[bagid];

    float4* o_inst = reinterpret_cast<float4*>(out + OFF_INST + (size_t)bagid * FF);
    float4* o_z    = reinterpret_cast<float4*>(out + OFF_Z    + (size_t)bagid * DD);
    float4* o_mu   = reinterpret_cast<float4*>(out + OFF_MU   + (size_t)bagid * DD);
    float4* o_sd   = reinterpret_cast<float4*>(out + OFF_STD  + (size_t)bagid * DD);

    if (p == 0ULL) {
        const float4 zero4 = make_float4(0.f, 0.f, 0.f, 0.f);
        if (tid == 0) out[OFF_M + bagid] = 0.f;
        for (int i = tid; i < FF / 4; i += blockDim.x) o_inst[i] = zero4;
        if (tid < DD / 4) { o_z[tid] = zero4; o_mu[tid] = zero4; o_sd[tid] = zero4; }
        return;
    }

    const int idx = NN - (int)(unsigned)(p & 0xFFFFFFFFu);
    if (tid == 0) out[OFF_M + bagid] = dec_float((unsigned)(p >> 32));

    const float4* s_inst = reinterpret_cast<const float4*>(inst + (size_t)idx * FF);
    const float4* s_z    = reinterpret_cast<const float4*>(z    + (size_t)idx * DD);
    const float4* s_mu   = reinterpret_cast<const float4*>(mu   + (size_t)idx * DD);
    const float4* s_sd   = reinterpret_cast<const float4*>(sd   + (size_t)idx * DD);

    for (int i = tid; i < FF / 4; i += blockDim.x) o_inst[i] = s_inst[i];
    if (tid < DD / 4) {
        o_z[tid]  = s_z[tid];
        o_mu[tid] = s_mu[tid];
        o_sd[tid] = s_sd[tid];
    }
}

extern "C" void kernel_launch(void* const* d_in, const int* in_sizes, int n_in,
                              void* d_out, int out_size) {
    const float* z_ins   = (const float*)d_in[0];
    const int*   bag_idx = (const int*)  d_in[1];
    const float* inst    = (const float*)d_in[2];
    const float* mu      = (const float*)d_in[3];
    const float* sd      = (const float*)d_in[4];
    const float* W       = (const float*)d_in[5];
    const float* b       = (const float*)d_in[6];
    float* out = (float*)d_out;

    init_seg_kernel<<<(BB + 255) / 256, 256>>>();

    // 8 warps/block, warp per row.
    const int warps_per_block = 8;
    const int blocks = (NN + warps_per_block - 1) / warps_per_block;
    loc_kernel<<<blocks, warps_per_block * 32>>>(z_ins, bag_idx, W, b, out + OFF_LOC);

    gather_kernel<<<BB, 128>>>(z_ins, inst, mu, sd, out);
}

// round 4
// speedup vs baseline: 1.4595x; 1.4595x over previous
#include <cuda_runtime.h>
#include <cstdint>

// Problem constants (fixed by the dataset)
#define NN 250000
#define DD 128
#define FF 512
#define BB 5000

// Output layout (tuple order, row-major, concatenated):
#define OFF_M        0
#define OFF_INST     5000
#define OFF_Z        2565000
#define OFF_LOC      3205000
#define OFF_MU       3455000
#define OFF_STD      4095000

// Per-bag packed (encoded loc | (N - index)) argmax scratch.
// Zero at module load; gather_kernel re-zeroes after each consume, so no
// init kernel is needed and graph replays stay deterministic.
__device__ unsigned long long g_seg[BB];

// Order-preserving bijection float -> uint32 (monotonic, injective).
__device__ __forceinline__ unsigned enc_float(float f) {
    unsigned bits = __float_as_uint(f);
    return (bits & 0x80000000u) ? ~bits : (bits | 0x80000000u);
}
__device__ __forceinline__ float dec_float(unsigned e) {
    unsigned bits = (e & 0x80000000u) ? (e ^ 0x80000000u) : ~e;
    return __uint_as_float(bits);
}

#define ROWS_PER_WARP 4

// Warp handles 4 rows: loads front-batched (MLP=4), then 4 pipelined
// butterfly reductions; lanes 0..3 each finalize one row.
__global__ void __launch_bounds__(256) loc_kernel(
        const float* __restrict__ z,
        const int*   __restrict__ bag,
        const float* __restrict__ W,
        const float* __restrict__ b,
        float*       __restrict__ loc_out) {
    const int warp = (blockIdx.x * blockDim.x + threadIdx.x) >> 5;
    const int lane = threadIdx.x & 31;
    const int row0 = warp * ROWS_PER_WARP;
    if (row0 >= NN) return;

    const float4 wv = __ldg(&reinterpret_cast<const float4*>(W)[lane]);

    // Front-batch the 4 row loads (independent -> MLP=4).
    float4 zv[ROWS_PER_WARP];
    const float4* z4 = reinterpret_cast<const float4*>(z) + (size_t)row0 * (DD / 4) + lane;
    #pragma unroll
    for (int r = 0; r < ROWS_PER_WARP; r++) {
        if (row0 + r < NN) zv[r] = z4[(size_t)r * (DD / 4)];
        else               zv[r] = make_float4(0.f, 0.f, 0.f, 0.f);
    }

    float s0 = fmaf(zv[0].x, wv.x, fmaf(zv[0].y, wv.y, fmaf(zv[0].z, wv.z, zv[0].w * wv.w)));
    float s1 = fmaf(zv[1].x, wv.x, fmaf(zv[1].y, wv.y, fmaf(zv[1].z, wv.z, zv[1].w * wv.w)));
    float s2 = fmaf(zv[2].x, wv.x, fmaf(zv[2].y, wv.y, fmaf(zv[2].z, wv.z, zv[2].w * wv.w)));
    float s3 = fmaf(zv[3].x, wv.x, fmaf(zv[3].y, wv.y, fmaf(zv[3].z, wv.z, zv[3].w * wv.w)));

    #pragma unroll
    for (int off = 16; off; off >>= 1) {
        s0 += __shfl_xor_sync(0xFFFFFFFFu, s0, off);
        s1 += __shfl_xor_sync(0xFFFFFFFFu, s1, off);
        s2 += __shfl_xor_sync(0xFFFFFFFFu, s2, off);
        s3 += __shfl_xor_sync(0xFFFFFFFFu, s3, off);
    }

    if (lane < ROWS_PER_WARP) {
        const int row = row0 + lane;
        if (row < NN) {
            float v = (lane == 0) ? s0 : (lane == 1) ? s1 : (lane == 2) ? s2 : s3;
            v += __ldg(b);
            loc_out[row] = v;
            unsigned long long packed =
                ((unsigned long long)enc_float(v) << 32) | (unsigned)(NN - row);
            atomicMax(&g_seg[bag[row]], packed);  // no return use -> REDG path
        }
    }
}

// One block per bag: decode argmax, gather rows (float4 copies), write M,
// then reset the scratch slot for the next graph replay.
__global__ void __launch_bounds__(128) gather_kernel(
        const float* __restrict__ z,
        const float* __restrict__ inst,
        const float* __restrict__ mu,
        const float* __restrict__ sd,
        float*       __restrict__ out) {
    const int bagid = blockIdx.x;
    const int tid   = threadIdx.x;

    const unsigned long long p = g_seg[bagid];

    float4* o_inst = reinterpret_cast<float4*>(out + OFF_INST + (size_t)bagid * FF);
    float4* o_z    = reinterpret_cast<float4*>(out + OFF_Z    + (size_t)bagid * DD);
    float4* o_mu   = reinterpret_cast<float4*>(out + OFF_MU   + (size_t)bagid * DD);
    float4* o_sd   = reinterpret_cast<float4*>(out + OFF_STD  + (size_t)bagid * DD);

    if (p == 0ULL) {
        // Empty bag: zero fill (scratch already 0, no reset needed).
        const float4 zero4 = make_float4(0.f, 0.f, 0.f, 0.f);
        if (tid == 0) out[OFF_M + bagid] = 0.f;
        for (int i = tid; i < FF / 4; i += blockDim.x) o_inst[i] = zero4;
        if (tid < DD / 4) { o_z[tid] = zero4; o_mu[tid] = zero4; o_sd[tid] = zero4; }
        return;
    }

    const int idx = NN - (int)(unsigned)(p & 0xFFFFFFFFu);
    if (tid == 0) out[OFF_M + bagid] = dec_float((unsigned)(p >> 32));

    const float4* s_inst = reinterpret_cast<const float4*>(inst + (size_t)idx * FF);
    const float4* s_z    = reinterpret_cast<const float4*>(z    + (size_t)idx * DD);
    const float4* s_mu   = reinterpret_cast<const float4*>(mu   + (size_t)idx * DD);
    const float4* s_sd   = reinterpret_cast<const float4*>(sd   + (size_t)idx * DD);

    for (int i = tid; i < FF / 4; i += blockDim.x) o_inst[i] = s_inst[i];
    if (tid < DD / 4) {
        o_z[tid]  = s_z[tid];
        o_mu[tid] = s_mu[tid];
        o_sd[tid] = s_sd[tid];
    }

    // All threads have read p; reset scratch for the next replay.
    __syncthreads();
    if (tid == 0) g_seg[bagid] = 0ULL;
}

extern "C" void kernel_launch(void* const* d_in, const int* in_sizes, int n_in,
                              void* d_out, int out_size) {
    const float* z_ins   = (const float*)d_in[0];
    const int*   bag_idx = (const int*)  d_in[1];
    const float* inst    = (const float*)d_in[2];
    const float* mu      = (const float*)d_in[3];
    const float* sd      = (const float*)d_in[4];
    const float* W       = (const float*)d_in[5];
    const float* b       = (const float*)d_in[6];
    float* out = (float*)d_out;

    // 8 warps/block, 4 rows/warp -> 32 rows/block.
    const int rows_per_block = 8 * ROWS_PER_WARP;
    const int blocks = (NN + rows_per_block - 1) / rows_per_block;
    loc_kernel<<<blocks, 256>>>(z_ins, bag_idx, W, b, out + OFF_LOC);

    gather_kernel<<<BB, 128>>>(z_ins, inst, mu, sd, out);
}

// round 5
// speedup vs baseline: 1.4608x; 1.0009x over previous
#include <cuda_runtime.h>
#include <cstdint>

// Problem constants (fixed by the dataset)
#define NN 250000
#define DD 128
#define FF 512
#define BB 5000

// Output layout (tuple order, row-major, concatenated):
#define OFF_M        0
#define OFF_INST     5000
#define OFF_Z        2565000
#define OFF_LOC      3205000
#define OFF_MU       3455000
#define OFF_STD      4095000

// Per-bag packed (encoded loc | (N - index)) argmax scratch.
// Zero at module load; gather_kernel re-zeroes after each consume, so no
// init kernel is needed and graph replays stay deterministic.
__device__ unsigned long long g_seg[BB];

// Order-preserving bijection float -> uint32 (monotonic, injective).
__device__ __forceinline__ unsigned enc_float(float f) {
    unsigned bits = __float_as_uint(f);
    return (bits & 0x80000000u) ? ~bits : (bits | 0x80000000u);
}
__device__ __forceinline__ float dec_float(unsigned e) {
    unsigned bits = (e & 0x80000000u) ? (e ^ 0x80000000u) : ~e;
    return __uint_as_float(bits);
}

#define ROWS_PER_WARP 4

// Warp handles 4 rows: loads front-batched (MLP=4), then 4 pipelined
// butterfly reductions; lanes 0..3 each finalize one row.
__global__ void __launch_bounds__(256) loc_kernel(
        const float* __restrict__ z,
        const int*   __restrict__ bag,
        const float* __restrict__ W,
        const float* __restrict__ b,
        float*       __restrict__ loc_out) {
    const int warp = (blockIdx.x * blockDim.x + threadIdx.x) >> 5;
    const int lane = threadIdx.x & 31;
    const int row0 = warp * ROWS_PER_WARP;
    if (row0 >= NN) return;

    const float4 wv = __ldg(&reinterpret_cast<const float4*>(W)[lane]);

    // Front-batch the 4 row loads (independent -> MLP=4).
    float4 zv[ROWS_PER_WARP];
    const float4* z4 = reinterpret_cast<const float4*>(z) + (size_t)row0 * (DD / 4) + lane;
    #pragma unroll
    for (int r = 0; r < ROWS_PER_WARP; r++) {
        if (row0 + r < NN) zv[r] = z4[(size_t)r * (DD / 4)];
        else               zv[r] = make_float4(0.f, 0.f, 0.f, 0.f);
    }

    float s0 = fmaf(zv[0].x, wv.x, fmaf(zv[0].y, wv.y, fmaf(zv[0].z, wv.z, zv[0].w * wv.w)));
    float s1 = fmaf(zv[1].x, wv.x, fmaf(zv[1].y, wv.y, fmaf(zv[1].z, wv.z, zv[1].w * wv.w)));
    float s2 = fmaf(zv[2].x, wv.x, fmaf(zv[2].y, wv.y, fmaf(zv[2].z, wv.z, zv[2].w * wv.w)));
    float s3 = fmaf(zv[3].x, wv.x, fmaf(zv[3].y, wv.y, fmaf(zv[3].z, wv.z, zv[3].w * wv.w)));

    #pragma unroll
    for (int off = 16; off; off >>= 1) {
        s0 += __shfl_xor_sync(0xFFFFFFFFu, s0, off);
        s1 += __shfl_xor_sync(0xFFFFFFFFu, s1, off);
        s2 += __shfl_xor_sync(0xFFFFFFFFu, s2, off);
        s3 += __shfl_xor_sync(0xFFFFFFFFu, s3, off);
    }

    if (lane < ROWS_PER_WARP) {
        const int row = row0 + lane;
        if (row < NN) {
            float v = (lane == 0) ? s0 : (lane == 1) ? s1 : (lane == 2) ? s2 : s3;
            v += __ldg(b);
            loc_out[row] = v;
            unsigned long long packed =
                ((unsigned long long)enc_float(v) << 32) | (unsigned)(NN - row);
            atomicMax(&g_seg[bag[row]], packed);  // no return use -> REDG path
        }
    }
}

// Each block handles TWO bags (b0 = blockIdx, b1 = blockIdx + BB/2).
// Both g_seg loads front-issued, then per-thread: 2 independent inst-row
// float4 loads + (for the first 3 warps) 2 small-row float4 loads -> MLP=4
// before any store. Empty bags handled branch-free: idx clamped to 0, row
// loaded anyway, zero selected at store.
__global__ void __launch_bounds__(128) gather_kernel(
        const float* __restrict__ z,
        const float* __restrict__ inst,
        const float* __restrict__ mu,
        const float* __restrict__ sd,
        float*       __restrict__ out) {
    const int tid = threadIdx.x;
    const int b0  = blockIdx.x;
    const int b1  = blockIdx.x + (BB / 2);

    const unsigned long long p0 = g_seg[b0];
    const unsigned long long p1 = g_seg[b1];

    const bool e0 = (p0 == 0ULL);
    const bool e1 = (p1 == 0ULL);
    const int idx0 = e0 ? 0 : (NN - (int)(unsigned)(p0 & 0xFFFFFFFFu));
    const int idx1 = e1 ? 0 : (NN - (int)(unsigned)(p1 & 0xFFFFFFFFu));

    // inst rows: FF/4 = 128 float4 per bag -> one per thread per bag.
    float4 v0 = reinterpret_cast<const float4*>(inst + (size_t)idx0 * FF)[tid];
    float4 v1 = reinterpret_cast<const float4*>(inst + (size_t)idx1 * FF)[tid];

    // Small rows: warp 0 -> z, warp 1 -> mu, warp 2 -> sd (DD/4 = 32 = warp).
    const int grp  = tid >> 5;
    const int lane = tid & 31;
    float4 s0v = make_float4(0.f, 0.f, 0.f, 0.f);
    float4 s1v = s0v;
    if (grp < 3) {
        const float* base = (grp == 0) ? z : (grp == 1) ? mu : sd;
        s0v = reinterpret_cast<const float4*>(base + (size_t)idx0 * DD)[lane];
        s1v = reinterpret_cast<const float4*>(base + (size_t)idx1 * DD)[lane];
    }

    const float4 zero4 = make_float4(0.f, 0.f, 0.f, 0.f);
    if (e0) v0 = zero4;
    if (e1) v1 = zero4;

    reinterpret_cast<float4*>(out + OFF_INST + (size_t)b0 * FF)[tid] = v0;
    reinterpret_cast<float4*>(out + OFF_INST + (size_t)b1 * FF)[tid] = v1;

    if (grp < 3) {
        if (e0) s0v = zero4;
        if (e1) s1v = zero4;
        const int off = (grp == 0) ? OFF_Z : (grp == 1) ? OFF_MU : OFF_STD;
        reinterpret_cast<float4*>(out + off + (size_t)b0 * DD)[lane] = s0v;
        reinterpret_cast<float4*>(out + off + (size_t)b1 * DD)[lane] = s1v;
    }

    if (tid == 0) out[OFF_M + b0] = e0 ? 0.f : dec_float((unsigned)(p0 >> 32));
    if (tid == 1) out[OFF_M + b1] = e1 ? 0.f : dec_float((unsigned)(p1 >> 32));

    // All warps have consumed p0/p1 (loaded at entry) -> barrier, then reset
    // the scratch slots so the next graph replay starts from zero.
    __syncthreads();
    if (tid == 0) g_seg[b0] = 0ULL;
    if (tid == 1) g_seg[b1] = 0ULL;
}

extern "C" void kernel_launch(void* const* d_in, const int* in_sizes, int n_in,
                              void* d_out, int out_size) {
    const float* z_ins   = (const float*)d_in[0];
    const int*   bag_idx = (const int*)  d_in[1];
    const float* inst    = (const float*)d_in[2];
    const float* mu      = (const float*)d_in[3];
    const float* sd      = (const float*)d_in[4];
    const float* W       = (const float*)d_in[5];
    const float* b       = (const float*)d_in[6];
    float* out = (float*)d_out;

    // 8 warps/block, 4 rows/warp -> 32 rows/block.
    const int rows_per_block = 8 * ROWS_PER_WARP;
    const int blocks = (NN + rows_per_block - 1) / rows_per_block;
    loc_kernel<<<blocks, 256>>>(z_ins, bag_idx, W, b, out + OFF_LOC);

    gather_kernel<<<BB / 2, 128>>>(z_ins, inst, mu, sd, out);
}